// round 17
// baseline (speedup 1.0000x reference)
#include <cuda_runtime.h>
#include <cuda_bf16.h>
#include <cuda_fp16.h>
#include <stdint.h>
#include <math.h>

#define N_MAX 100000
#define E_MAX 1600000
#define HD 128

// ---------------- device scratch (static; no allocations) ----------------
__device__ int   g_src[E_MAX];
__device__ int   g_dst[E_MAX];
__device__ int   g_deg[N_MAX];
__device__ int   g_rowStart[N_MAX + 1];
__device__ int   g_cursor[N_MAX];
__device__ float g_dinv[N_MAX];
__device__ unsigned g_scanstate[512];          // (state<<30 | sum), unsigned
__device__ int2  g_csr[E_MAX];                 // (src, dinv_src bits)
__device__ __half g_xw[(size_t)N_MAX * HD];    // xw (fp16)
__device__ __half g_h[(size_t)N_MAX * HD];     // h1/h2 (fp16)
// weights pre-converted to bf16 hi/lo, [k][128] row-major
__device__ __nv_bfloat16 g_w1hi[16384], g_w1lo[16384];
__device__ __nv_bfloat16 g_w2hi[16384], g_w2lo[16384];
__device__ __nv_bfloat16 g_fhi[18432],  g_flo[18432];

// ---------------- helpers -------------------------------------------------

__device__ __forceinline__ uint32_t smem_u32(const void* p) {
    uint32_t a;
    asm("{ .reg .u64 t; cvta.to.shared.u64 t, %1; cvt.u32.u64 %0, t; }"
        : "=r"(a) : "l"(p));
    return a;
}

__device__ __forceinline__ void ldsm_x4(uint32_t* r, uint32_t addr) {
    asm volatile("ldmatrix.sync.aligned.m8n8.x4.shared.b16 {%0,%1,%2,%3}, [%4];"
                 : "=r"(r[0]), "=r"(r[1]), "=r"(r[2]), "=r"(r[3]) : "r"(addr));
}

__device__ __forceinline__ void ldsm_x4_t(uint32_t* r, uint32_t addr) {
    asm volatile("ldmatrix.sync.aligned.m8n8.x4.trans.shared.b16 {%0,%1,%2,%3}, [%4];"
                 : "=r"(r[0]), "=r"(r[1]), "=r"(r[2]), "=r"(r[3]) : "r"(addr));
}

__device__ __forceinline__ void mma_bf16(float* c, const uint32_t* a, const uint32_t* b) {
    asm volatile(
        "mma.sync.aligned.m16n8k16.row.col.f32.bf16.bf16.f32 "
        "{%0,%1,%2,%3}, {%4,%5,%6,%7}, {%8,%9}, {%0,%1,%2,%3};"
        : "+f"(c[0]), "+f"(c[1]), "+f"(c[2]), "+f"(c[3])
        : "r"(a[0]), "r"(a[1]), "r"(a[2]), "r"(a[3]), "r"(b[0]), "r"(b[1]));
}

__device__ __forceinline__ uint32_t pack_bf2(__nv_bfloat16 a, __nv_bfloat16 b) {
    __nv_bfloat162 t;
    t.x = a; t.y = b;
    return *reinterpret_cast<uint32_t*>(&t);
}

__device__ __forceinline__ void split2(float x, float y, uint32_t& hi, uint32_t& lo) {
    __nv_bfloat16 hx = __float2bfloat16(x), hy = __float2bfloat16(y);
    __nv_bfloat16 lx = __float2bfloat16(x - __bfloat162float(hx));
    __nv_bfloat16 ly = __float2bfloat16(y - __bfloat162float(hy));
    hi = pack_bf2(hx, hy);
    lo = pack_bf2(lx, ly);
}

// ---------------- GEMM device body ----------------------------------------
// C[M,128] = A[M,K] @ W[K,128], D = hiA*hiB + hiA*loB + loA*hiB (fp32 acc).
// AH: A fp16 (split exact). !FC: out fp16 xw. FC: K=144, fused head, fp32 out.

#define AS_STRIDE 40   // 80B row stride -> conflict-free ldmatrix
#define BS_STRIDE 136  // 272B row stride -> conflict-free ldmatrix

template <bool AH, bool FC>
__device__ __forceinline__ void gemm_body(
    int bid, const void* __restrict__ Av, const float* __restrict__ ACT,
    const __nv_bfloat16* __restrict__ Bhi, const __nv_bfloat16* __restrict__ Blo,
    const float* __restrict__ B1, const float* __restrict__ W2v,
    const float* __restrict__ B2, void* __restrict__ OUTv, int M,
    __nv_bfloat16* sAhi, __nv_bfloat16* sAlo,
    __nv_bfloat16* sBhi, __nv_bfloat16* sBlo) {

    const int tid = threadIdx.x, wid = tid >> 5, lane = tid & 31;
    const int gid = lane >> 2, tg = lane & 3;
    const int wm = wid >> 2, wn = wid & 3;
    const int mbase = wm * 64, nbase = wn * 32;
    const int row0 = bid * 128;

    const float* Af = (const float*)Av;
    const __half* Ah = (const __half*)Av;

    const uint32_t uAhi = smem_u32(sAhi), uAlo = smem_u32(sAlo);
    const uint32_t uBhi = smem_u32(sBhi), uBlo = smem_u32(sBlo);

    float c[4][4][4];
#pragma unroll
    for (int i = 0; i < 4; i++)
#pragma unroll
        for (int j = 0; j < 4; j++)
#pragma unroll
            for (int q = 0; q < 4; q++) c[i][j][q] = 0.0f;

    const int KTOT = FC ? 144 : 128;
    const int srow = tid >> 1;
    const int skb = (tid & 1) * 16;
    const int sarow = row0 + srow;

    for (int k0 = 0; k0 < KTOT; k0 += 32) {
        const int kc = (KTOT - k0 < 32) ? (KTOT - k0) : 32;
        __syncthreads();
        if (skb < kc) {
#pragma unroll
            for (int i = 0; i < 4; i++) {
                float4 v = make_float4(0.f, 0.f, 0.f, 0.f);
                int kg = k0 + skb + i * 4;
                if (sarow < M) {
                    if (FC && kg >= 128) {
                        v = *(const float4*)(ACT + (size_t)sarow * 16 + (kg - 128));
                    } else if (AH) {
                        uint2 u = *(const uint2*)(Ah + (size_t)sarow * 128 + kg);
                        float2 f0 = __half22float2(*(__half2*)&u.x);
                        float2 f1 = __half22float2(*(__half2*)&u.y);
                        v = make_float4(f0.x, f0.y, f1.x, f1.y);
                    } else {
                        v = *(const float4*)(Af + (size_t)sarow * 128 + kg);
                    }
                }
                uint32_t h0, l0, h1, l1;
                split2(v.x, v.y, h0, l0);
                split2(v.z, v.w, h1, l1);
                int si = srow * AS_STRIDE + skb + i * 4;
                *(uint2*)(sAhi + si) = make_uint2(h0, h1);
                *(uint2*)(sAlo + si) = make_uint2(l0, l1);
            }
        }
        for (int idx = tid; idx < kc * 16; idx += 256) {
            int r = idx >> 4, cn = (idx & 15) * 8;
            *(uint4*)(sBhi + r * BS_STRIDE + cn) =
                *(const uint4*)(Bhi + (size_t)(k0 + r) * 128 + cn);
            *(uint4*)(sBlo + r * BS_STRIDE + cn) =
                *(const uint4*)(Blo + (size_t)(k0 + r) * 128 + cn);
        }
        __syncthreads();

        const int nkt = kc >> 4;
        for (int kt = 0; kt < nkt; kt++) {
            const int kk = kt * 16;
            const uint32_t aoff =
                (uint32_t)(((mbase + (lane & 15)) * AS_STRIDE + kk + (lane >> 4) * 8) * 2);
            const uint32_t boff =
                (uint32_t)(((kk + (lane & 15)) * BS_STRIDE + nbase + (lane >> 4) * 8) * 2);

            uint32_t ahi[4][4], b[4][2];
#pragma unroll
            for (int mt = 0; mt < 4; mt++)
                ldsm_x4(ahi[mt], uAhi + aoff + (uint32_t)(mt * 16 * AS_STRIDE * 2));
#pragma unroll
            for (int p = 0; p < 2; p++) {
                uint32_t r4[4];
                ldsm_x4_t(r4, uBhi + boff + (uint32_t)(p * 32));
                b[2 * p][0] = r4[0]; b[2 * p][1] = r4[1];
                b[2 * p + 1][0] = r4[2]; b[2 * p + 1][1] = r4[3];
            }
#pragma unroll
            for (int mt = 0; mt < 4; mt++)
#pragma unroll
                for (int nt = 0; nt < 4; nt++) mma_bf16(c[mt][nt], ahi[mt], b[nt]);
            {
                uint32_t alo[4][4];
#pragma unroll
                for (int mt = 0; mt < 4; mt++)
                    ldsm_x4(alo[mt], uAlo + aoff + (uint32_t)(mt * 16 * AS_STRIDE * 2));
#pragma unroll
                for (int mt = 0; mt < 4; mt++)
#pragma unroll
                    for (int nt = 0; nt < 4; nt++) mma_bf16(c[mt][nt], alo[mt], b[nt]);
            }
#pragma unroll
            for (int p = 0; p < 2; p++) {
                uint32_t r4[4];
                ldsm_x4_t(r4, uBlo + boff + (uint32_t)(p * 32));
                b[2 * p][0] = r4[0]; b[2 * p][1] = r4[1];
                b[2 * p + 1][0] = r4[2]; b[2 * p + 1][1] = r4[3];
            }
#pragma unroll
            for (int mt = 0; mt < 4; mt++)
#pragma unroll
                for (int nt = 0; nt < 4; nt++) mma_bf16(c[mt][nt], ahi[mt], b[nt]);
        }
    }

    if (!FC) {
        __half* Oh = (__half*)OUTv;
#pragma unroll
        for (int mt = 0; mt < 4; mt++) {
            int rlo = row0 + mbase + mt * 16 + gid;
            int rhi = rlo + 8;
#pragma unroll
            for (int nt = 0; nt < 4; nt++) {
                int col = nbase + nt * 8 + tg * 2;
                if (rlo < M)
                    *(__half2*)(Oh + (size_t)rlo * 128 + col) =
                        __floats2half2_rn(c[mt][nt][0], c[mt][nt][1]);
                if (rhi < M)
                    *(__half2*)(Oh + (size_t)rhi * 128 + col) =
                        __floats2half2_rn(c[mt][nt][2], c[mt][nt][3]);
            }
        }
    } else {
        float* OUT = (float*)OUTv;
        float b1v[4][2], w2v[4][2];
#pragma unroll
        for (int nt = 0; nt < 4; nt++) {
            int col = nbase + nt * 8 + tg * 2;
            b1v[nt][0] = B1[col];     b1v[nt][1] = B1[col + 1];
            w2v[nt][0] = W2v[col];    w2v[nt][1] = W2v[col + 1];
        }
        __syncthreads();
        float* red = (float*)sAhi;  // [128][4]
#pragma unroll
        for (int mt = 0; mt < 4; mt++) {
            float plo = 0.f, phi = 0.f;
#pragma unroll
            for (int nt = 0; nt < 4; nt++) {
                plo += fmaxf(c[mt][nt][0] + b1v[nt][0], 0.f) * w2v[nt][0]
                     + fmaxf(c[mt][nt][1] + b1v[nt][1], 0.f) * w2v[nt][1];
                phi += fmaxf(c[mt][nt][2] + b1v[nt][0], 0.f) * w2v[nt][0]
                     + fmaxf(c[mt][nt][3] + b1v[nt][1], 0.f) * w2v[nt][1];
            }
            plo += __shfl_xor_sync(0xFFFFFFFFu, plo, 1);
            plo += __shfl_xor_sync(0xFFFFFFFFu, plo, 2);
            phi += __shfl_xor_sync(0xFFFFFFFFu, phi, 1);
            phi += __shfl_xor_sync(0xFFFFFFFFu, phi, 2);
            if (tg == 0) {
                red[(mbase + mt * 16 + gid) * 4 + wn] = plo;
                red[(mbase + mt * 16 + gid + 8) * 4 + wn] = phi;
            }
        }
        __syncthreads();
        if (tid < 128) {
            int r = row0 + tid;
            if (r < M) {
                OUT[r] = red[tid * 4 + 0] + red[tid * 4 + 1] +
                         red[tid * 4 + 2] + red[tid * 4 + 3] + B2[0];
            }
        }
    }
}

// ---------------- extract device body -------------------------------------
__device__ __forceinline__ void extract_body(const unsigned int* __restrict__ ebuf,
                                             int e, int blk, int nblk, int* s_is64) {
    if (threadIdx.x < 32) {
        int z = (ebuf[2 * threadIdx.x + 1] == 0u) ? 1 : 0;
        unsigned m = __ballot_sync(0xFFFFFFFFu, z);
        if (threadIdx.x == 0) *s_is64 = (m == 0xFFFFFFFFu);
    }
    __syncthreads();
    bool is64 = *s_is64;
    for (int i = blk * 256 + threadIdx.x; i < e; i += nblk * 256) {
        int s, d;
        if (is64) {
            uint2 us = *(const uint2*)(ebuf + 2 * (size_t)i);
            uint2 ud = *(const uint2*)(ebuf + 2 * ((size_t)e + i));
            s = (int)us.x;
            d = (int)ud.x;
        } else {
            s = (int)ebuf[i];
            d = (int)ebuf[e + i];
        }
        g_src[i] = s;
        g_dst[i] = d;
        atomicAdd(&g_deg[d], 1);
    }
}

// ---------------- kernels --------------------------------------------------

// prep: zero deg + scan flags + weight pre-convert
__global__ void prep_kernel(int n, const float* __restrict__ w1,
                            const float* __restrict__ w2,
                            const float* __restrict__ fw1) {
    int i = blockIdx.x * blockDim.x + threadIdx.x;
    if (i < n) g_deg[i] = 0;
    if (i < 512) g_scanstate[i] = 0u;
    if (i < 16384) {
        float v = w1[i];
        __nv_bfloat16 h = __float2bfloat16(v);
        g_w1hi[i] = h;
        g_w1lo[i] = __float2bfloat16(v - __bfloat162float(h));
    } else if (i < 32768) {
        int o = i - 16384;
        float v = w2[o];
        __nv_bfloat16 h = __float2bfloat16(v);
        g_w2hi[o] = h;
        g_w2lo[o] = __float2bfloat16(v - __bfloat162float(h));
    } else if (i < 51200) {
        int o = i - 32768;
        float v = fw1[o];
        __nv_bfloat16 h = __float2bfloat16(v);
        g_fhi[o] = h;
        g_flo[o] = __float2bfloat16(v - __bfloat162float(h));
    }
}

// phase1: blocks [0,GB) run GEMM1 (x fp32 @ W1 -> xw fp16);
//         blocks [GB, GB+EB) run extract grid-stride.
__global__ __launch_bounds__(256, 2)
void phase1_kernel(const float* __restrict__ x,
                   const __nv_bfloat16* __restrict__ Bhi,
                   const __nv_bfloat16* __restrict__ Blo,
                   __half* __restrict__ xw, int M, int GB,
                   const unsigned int* __restrict__ ebuf, int e, int EB) {
    __shared__ __align__(16) __nv_bfloat16 sAhi[128 * AS_STRIDE];
    __shared__ __align__(16) __nv_bfloat16 sAlo[128 * AS_STRIDE];
    __shared__ __align__(16) __nv_bfloat16 sBhi[32 * BS_STRIDE];
    __shared__ __align__(16) __nv_bfloat16 sBlo[32 * BS_STRIDE];
    __shared__ int s_is64;
    if (blockIdx.x < (unsigned)GB) {
        gemm_body<false, false>(blockIdx.x, x, nullptr, Bhi, Blo,
                                nullptr, nullptr, nullptr, xw, M,
                                sAhi, sAlo, sBhi, sBlo);
    } else {
        extract_body(ebuf, e, blockIdx.x - GB, EB, &s_is64);
    }
}

// fused decoupled-lookback scan: g_deg -> rowStart/cursor, + dinv.
// State word (UNSIGNED): 0 = not ready, 1<<30|agg, 2<<30|inclusive prefix.
__global__ void scan_kernel(int n, int e) {
    __shared__ int ws[8];
    __shared__ int s_prefix;
    const int b = blockIdx.x, tid = threadIdx.x, lane = tid & 31, w = tid >> 5;
    int i = b * 256 + tid;
    int v = (i < n) ? g_deg[i] : 0;
    if (i < n) g_dinv[i] = rsqrtf((float)(v + 1));
    int incl = v;
#pragma unroll
    for (int o = 1; o < 32; o <<= 1) {
        int t = __shfl_up_sync(0xFFFFFFFFu, incl, o);
        if (lane >= o) incl += t;
    }
    if (lane == 31) ws[w] = incl;
    __syncthreads();
    if (w == 0 && lane < 8) {
        int s = ws[lane];
#pragma unroll
        for (int o = 1; o < 8; o <<= 1) {
            int t = __shfl_up_sync(0xFFu, s, o);
            if (lane >= o) s += t;
        }
        ws[lane] = s;
    }
    __syncthreads();
    int blocksum = ws[7];
    if (tid == 0)
        atomicExch((unsigned*)&g_scanstate[b], 0x40000000u | (unsigned)blocksum);
    if (w == 0) {
        int prefix = 0;
        int idx = b - 1;
        while (idx >= 0) {
            int j = idx - lane;
            unsigned s = (j >= 0) ? (unsigned)__ldcg((const int*)&g_scanstate[j])
                                  : 0x80000000u;  // sentinel: prefix 0
            unsigned state = s >> 30;  // unsigned shift: 0 / 1 / 2
            unsigned b2 = __ballot_sync(0xFFFFFFFFu, state == 2u);
            unsigned b0 = __ballot_sync(0xFFFFFFFFu, state == 0u);
            int l2 = b2 ? (__ffs(b2) - 1) : 32;
            int l0 = b0 ? (__ffs(b0) - 1) : 32;
            if (l2 < l0) {
                int val = (lane <= l2) ? (int)(s & 0x3FFFFFFFu) : 0;
#pragma unroll
                for (int o = 16; o; o >>= 1) val += __shfl_xor_sync(0xFFFFFFFFu, val, o);
                prefix += val;
                break;
            } else {
                int val = (lane < l0) ? (int)(s & 0x3FFFFFFFu) : 0;
#pragma unroll
                for (int o = 16; o; o >>= 1) val += __shfl_xor_sync(0xFFFFFFFFu, val, o);
                prefix += val;
                idx -= l0;
            }
        }
        if (lane == 0) {
            atomicExch((unsigned*)&g_scanstate[b],
                       0x80000000u | (unsigned)(prefix + blocksum));
            s_prefix = prefix;
        }
    }
    __syncthreads();
    int excl = s_prefix + (w ? ws[w - 1] : 0) + incl - v;
    if (i < n) {
        g_rowStart[i] = excl;
        g_cursor[i] = excl;
    }
    if (i == 0) g_rowStart[n] = e;
}

// fill: 4 edges per thread -> 4 independent atomics in flight (MLP=4)
__global__ void fill_kernel(int e) {
    int i = (blockIdx.x * blockDim.x + threadIdx.x) * 4;
    if (i >= e) return;
    if (i + 3 < e) {
        int4 d4 = *(const int4*)(g_dst + i);
        int4 s4 = *(const int4*)(g_src + i);
        int p0 = atomicAdd(&g_cursor[d4.x], 1);
        int p1 = atomicAdd(&g_cursor[d4.y], 1);
        int p2 = atomicAdd(&g_cursor[d4.z], 1);
        int p3 = atomicAdd(&g_cursor[d4.w], 1);
        g_csr[p0] = make_int2(s4.x, __float_as_int(g_dinv[s4.x]));
        g_csr[p1] = make_int2(s4.y, __float_as_int(g_dinv[s4.y]));
        g_csr[p2] = make_int2(s4.z, __float_as_int(g_dinv[s4.z]));
        g_csr[p3] = make_int2(s4.w, __float_as_int(g_dinv[s4.w]));
    } else {
        for (int j = i; j < e; j++) {
            int d = g_dst[j], s = g_src[j];
            int pos = atomicAdd(&g_cursor[d], 1);
            g_csr[pos] = make_int2(s, __float_as_int(g_dinv[s]));
        }
    }
}

// standalone GEMM wrappers
template <bool AH, bool FC>
__global__ __launch_bounds__(256, 2)
void gemm_mma_kernel(const void* __restrict__ Av, const float* __restrict__ ACT,
                     const __nv_bfloat16* __restrict__ Bhi,
                     const __nv_bfloat16* __restrict__ Blo,
                     const float* __restrict__ B1, const float* __restrict__ W2v,
                     const float* __restrict__ B2, void* __restrict__ OUTv, int M) {
    __shared__ __align__(16) __nv_bfloat16 sAhi[128 * AS_STRIDE];
    __shared__ __align__(16) __nv_bfloat16 sAlo[128 * AS_STRIDE];
    __shared__ __align__(16) __nv_bfloat16 sBhi[32 * BS_STRIDE];
    __shared__ __align__(16) __nv_bfloat16 sBlo[32 * BS_STRIDE];
    gemm_body<AH, FC>(blockIdx.x, Av, ACT, Bhi, Blo, B1, W2v, B2, OUTv, M,
                      sAhi, sAlo, sBhi, sBlo);
}

// ------- aggregation: h = relu(di*(di*self + sum dinv_s * row) + b) -------
// 2 nodes per warp: 16 lanes x uint4 (16B) per row; one LDG.128 = 2 edges.

__global__ void agg_kernel(const __half* __restrict__ XW,
                           const float* __restrict__ B,
                           __half* __restrict__ OUT, int n) {
    const int warp = (blockIdx.x * blockDim.x + threadIdx.x) >> 5;
    const int lane = threadIdx.x & 31;
    const int half = lane >> 4;     // which node of the pair
    const int hl = lane & 15;       // lane within half-warp
    const int node = warp * 2 + half;
    const bool valid = node < n;

    float di = valid ? g_dinv[node] : 0.f;
    float acc[8];
    if (valid) {
        uint4 u = ((const uint4*)(XW + (size_t)node * 128))[hl];
        float2 f0 = __half22float2(*(__half2*)&u.x);
        float2 f1 = __half22float2(*(__half2*)&u.y);
        float2 f2 = __half22float2(*(__half2*)&u.z);
        float2 f3 = __half22float2(*(__half2*)&u.w);
        acc[0] = f0.x * di; acc[1] = f0.y * di;
        acc[2] = f1.x * di; acc[3] = f1.y * di;
        acc[4] = f2.x * di; acc[5] = f2.y * di;
        acc[6] = f3.x * di; acc[7] = f3.y * di;
    } else {
#pragma unroll
        for (int j = 0; j < 8; j++) acc[j] = 0.f;
    }

    int p  = valid ? g_rowStart[node] : 0;
    int pe = valid ? g_rowStart[node + 1] : 0;

#define AGG_EDGE(EID)                                                         \
    do {                                                                      \
        float nn = __int_as_float((EID).y);                                   \
        uint4 u = ((const uint4*)(XW + (size_t)(EID).x * 128))[hl];           \
        float2 f0 = __half22float2(*(__half2*)&u.x);                          \
        float2 f1 = __half22float2(*(__half2*)&u.y);                          \
        float2 f2 = __half22float2(*(__half2*)&u.z);                          \
        float2 f3 = __half22float2(*(__half2*)&u.w);                          \
        acc[0] += nn * f0.x; acc[1] += nn * f0.y;                             \
        acc[2] += nn * f1.x; acc[3] += nn * f1.y;                             \
        acc[4] += nn * f2.x; acc[5] += nn * f2.y;                             \
        acc[6] += nn * f3.x; acc[7] += nn * f3.y;                             \
    } while (0)

    for (; p + 3 < pe; p += 4) {
        int2 e0 = g_csr[p],     e1 = g_csr[p + 1];
        int2 e2 = g_csr[p + 2], e3 = g_csr[p + 3];
        AGG_EDGE(e0);
        AGG_EDGE(e1);
        AGG_EDGE(e2);
        AGG_EDGE(e3);
    }
    for (; p < pe; p++) {
        int2 e0 = g_csr[p];
        AGG_EDGE(e0);
    }
#undef AGG_EDGE

    if (valid) {
        float4 ba = ((const float4*)B)[hl * 2];
        float4 bb = ((const float4*)B)[hl * 2 + 1];
        __half2 o0 = __floats2half2_rn(fmaxf(acc[0] * di + ba.x, 0.f),
                                       fmaxf(acc[1] * di + ba.y, 0.f));
        __half2 o1 = __floats2half2_rn(fmaxf(acc[2] * di + ba.z, 0.f),
                                       fmaxf(acc[3] * di + ba.w, 0.f));
        __half2 o2 = __floats2half2_rn(fmaxf(acc[4] * di + bb.x, 0.f),
                                       fmaxf(acc[5] * di + bb.y, 0.f));
        __half2 o3 = __floats2half2_rn(fmaxf(acc[6] * di + bb.z, 0.f),
                                       fmaxf(acc[7] * di + bb.w, 0.f));
        uint4 ov = make_uint4(*(uint32_t*)&o0, *(uint32_t*)&o1,
                              *(uint32_t*)&o2, *(uint32_t*)&o3);
        ((uint4*)(OUT + (size_t)node * 128))[hl] = ov;
    }
}

// ---------------- launch --------------------------------------------------

extern "C" void kernel_launch(void* const* d_in, const int* in_sizes, int n_in,
                              void* d_out, int out_size) {
    const float* x = (const float*)d_in[0];
    const unsigned int* eidx = (const unsigned int*)d_in[1];
    const float* action = (const float*)d_in[2];
    const float* w1 = (const float*)d_in[3];
    const float* b1 = (const float*)d_in[4];
    const float* w2 = (const float*)d_in[5];
    const float* b2 = (const float*)d_in[6];
    const float* fw1 = (const float*)d_in[7];
    const float* fb1 = (const float*)d_in[8];
    const float* fw2 = (const float*)d_in[9];
    const float* fb2 = (const float*)d_in[10];
    float* out = (float*)d_out;

    int n = in_sizes[0] / HD;  // 100000
    int e = in_sizes[1] / 2;   // 1600000

    void *pX = nullptr, *pH = nullptr;
    cudaGetSymbolAddress(&pX, g_xw);
    cudaGetSymbolAddress(&pH, g_h);
    __half* xw = (__half*)pX;
    __half* hbuf = (__half*)pH;

    void *p_w1h, *p_w1l, *p_w2h, *p_w2l, *p_fh, *p_fl;
    cudaGetSymbolAddress(&p_w1h, g_w1hi);
    cudaGetSymbolAddress(&p_w1l, g_w1lo);
    cudaGetSymbolAddress(&p_w2h, g_w2hi);
    cudaGetSymbolAddress(&p_w2l, g_w2lo);
    cudaGetSymbolAddress(&p_fh, g_fhi);
    cudaGetSymbolAddress(&p_fl, g_flo);

    int nblk = (n + 255) / 256;               // 391
    int gemm_grid = (n + 127) / 128;          // 782
    int agg_grid = ((n + 1) / 2 * 32 + 255) / 256;  // 6250
    int fill_grid = (e + 1023) / 1024;        // 1563
    int EB = 1024;                            // extract blocks inside phase1

    // 1. prep: zero deg/flags + weight convert
    prep_kernel<<<nblk, 256>>>(n, w1, w2, fw1);
    // 2. phase1: GEMM1 and extract concurrently
    phase1_kernel<<<gemm_grid + EB, 256>>>(
        x, (const __nv_bfloat16*)p_w1h, (const __nv_bfloat16*)p_w1l,
        xw, n, gemm_grid, eidx, e, EB);
    // 3. fused scan (deg -> rowStart/cursor, dinv)
    scan_kernel<<<nblk, 256>>>(n, e);
    // 4. CSR fill (4 edges/thread)
    fill_kernel<<<fill_grid, 256>>>(e);
    // 5. layer-1 aggregation
    agg_kernel<<<agg_grid, 256>>>(xw, b1, hbuf, n);
    // 6. GEMM2
    gemm_mma_kernel<true, false><<<gemm_grid, 256>>>(
        hbuf, nullptr, (const __nv_bfloat16*)p_w2h, (const __nv_bfloat16*)p_w2l,
        nullptr, nullptr, nullptr, xw, n);
    // 7. layer-2 aggregation
    agg_kernel<<<agg_grid, 256>>>(xw, b2, hbuf, n);
    // 8. fused FC head
    gemm_mma_kernel<true, true><<<gemm_grid, 256>>>(
        hbuf, action, (const __nv_bfloat16*)p_fh, (const __nv_bfloat16*)p_fl,
        fb1, fw2, fb2, out, n);
}